// round 2
// baseline (speedup 1.0000x reference)
#include <cuda_runtime.h>

// ExtractPatch: B=8, H=W=1024, N=4096 matches, R=8 -> 17x17 patches.
// Output (B, N, 2*289) fp32: [normalize(p1), normalize(p2)] per match.
// p1[k] = image1[b, m1 + k%17 - 8, m0 + k/17 - 8]  (zero outside [0,1024))
// normalize: (p - mean) / (std_ddof1 + 1e-4)

#define D      17
#define PATCH  289          // D*D
#define RADIUS 8
#define HW     1024
#define NMATCH 4096
#define BATCH  8
#define WARPS_PER_BLOCK 4
#define THREADS (WARPS_PER_BLOCK * 32)

__global__ __launch_bounds__(THREADS, 12)
void extract_patch_kernel(const float* __restrict__ img1,
                          const float* __restrict__ img2,
                          const int*   __restrict__ matches,
                          float*       __restrict__ out)
{
    // +19 pad (odd stride) -> conflict-free transposed reads
    __shared__ float smem[WARPS_PER_BLOCK][D][19];

    const int warpId = threadIdx.x >> 5;
    const int lane   = threadIdx.x & 31;

    // global patch id: 2 patches (img1/img2) per (b, n)
    const int gp    = blockIdx.x * WARPS_PER_BLOCK + warpId;   // 0 .. 65535
    const int which = gp & 1;                                  // 0 -> p1, 1 -> p2
    const int bn    = gp >> 1;                                 // b*NMATCH + n
    const int b     = bn >> 12;                                // NMATCH = 4096

    const float* __restrict__ img = which ? img2 : img1;
    const float* __restrict__ ib  = img + (size_t)b * (HW * HW);

    // 8B vector load of (mx, my)
    const int2 mv = *(const int2*)(matches + bn * 4 + which * 2);
    const int  mx = mv.x;   // column base
    const int  my = mv.y;   // row base

    // ---- load patch in IMAGE-ROW order (coalesced), accumulate sum/sumsq ----
    // idx = t*32 + lane, row = idx/17, col = idx%17 maintained incrementally:
    // idx += 32  <=>  col += 15, row += 1, carry if col >= 17.
    float sum = 0.f, sumsq = 0.f;
    {
        int row = (lane >= D) ? 1 : 0;
        int col = (lane >= D) ? (lane - D) : lane;
        #pragma unroll
        for (int t = 0; t < 10; ++t) {
            if (t < 9 || lane == 0) {
                const int y = my + row - RADIUS;
                const int x = mx + col - RADIUS;
                float v = 0.f;
                if (((unsigned)y < HW) & ((unsigned)x < HW))
                    v = __ldg(ib + y * HW + x);
                smem[warpId][row][col] = v;
                sum   += v;
                sumsq  = fmaf(v, v, sumsq);
            }
            // advance by 32
            col += 15; row += 1;
            if (col >= D) { col -= D; row += 1; }
        }
    }

    // ---- warp reduction for mean / unbiased std ----
    #pragma unroll
    for (int o = 16; o > 0; o >>= 1) {
        sum   += __shfl_xor_sync(0xffffffffu, sum,   o);
        sumsq += __shfl_xor_sync(0xffffffffu, sumsq, o);
    }
    const float mean = sum * (1.0f / PATCH);
    float var = (sumsq - (float)PATCH * mean * mean) * (1.0f / (PATCH - 1));
    var = fmaxf(var, 0.0f);
    const float inv = 1.0f / (sqrtf(var) + 1e-4f);

    __syncwarp();

    // ---- transposed, normalized, coalesced streaming write ----
    // out index k = t*32 + lane; v = smem[k%17][k/17]; same incremental walk.
    float* __restrict__ ob = out + (size_t)bn * (2 * PATCH) + which * PATCH;
    {
        int r = (lane >= D) ? (lane - D) : lane;
        int c = (lane >= D) ? 1 : 0;
        #pragma unroll
        for (int t = 0; t < 10; ++t) {
            if (t < 9 || lane == 0) {
                const float v = smem[warpId][r][c];
                __stcs(ob + t * 32 + lane, (v - mean) * inv);
            }
            r += 15; c += 1;
            if (r >= D) { r -= D; c += 1; }
        }
    }
}

extern "C" void kernel_launch(void* const* d_in, const int* in_sizes, int n_in,
                              void* d_out, int out_size)
{
    const float* img1    = (const float*)d_in[0];
    const float* img2    = (const float*)d_in[1];
    const int*   matches = (const int*)d_in[2];
    float*       out     = (float*)d_out;

    const int total_patches = BATCH * NMATCH * 2;              // 65536
    const int blocks = total_patches / WARPS_PER_BLOCK;        // 16384

    extract_patch_kernel<<<blocks, THREADS>>>(img1, img2, matches, out);
}

// round 4
// speedup vs baseline: 1.2790x; 1.2790x over previous
#include <cuda_runtime.h>

// ExtractPatch: B=8, H=W=1024, N=4096 matches, R=8 -> 17x17 patches.
// out[bn][k]        = normalize(img1[b, my1 + k%17 - 8, mx1 + k/17 - 8])   k in [0,289)
// out[bn][289 + k]  = normalize(img2[b, my2 + k%17 - 8, mx2 + k/17 - 8])
// normalize: (p - mean) / (std_ddof1 + 1e-4), zero-padded outside image.

#define D      17
#define PATCH  289
#define HW     1024
#define NMATCH 4096
#define BATCH  8
#define WPB    4              // warps per block, one match per warp
#define THREADS (WPB * 32)

__global__ __launch_bounds__(THREADS, 8)
void extract_patch_kernel(const float* __restrict__ img1,
                          const float* __restrict__ img2,
                          const int*   __restrict__ matches,
                          float*       __restrict__ out)
{
    // Transposed patch buffers: T[k] = output element k (both patches concat).
    __shared__ float T[WPB][580];

    const int warpId = threadIdx.x >> 5;
    const int lane   = threadIdx.x & 31;

    const int bn = blockIdx.x * WPB + warpId;     // 0 .. 32767
    const int b  = bn >> 12;                      // NMATCH = 4096

    const float* __restrict__ ib1 = img1 + (size_t)b * (HW * HW);
    const float* __restrict__ ib2 = img2 + (size_t)b * (HW * HW);

    const int4 m = *(const int4*)(matches + bn * 4);   // mx1, my1, mx2, my2

    float* __restrict__ Tw = T[warpId];

    // initial (r, c) for this lane: idx = lane, r = idx/17, c = idx%17
    int c0 = (lane >= D) ? (lane - D) : lane;
    int r0 = (lane >= D) ? 1 : 0;

    float s1 = 0.f, q1 = 0.f, s2 = 0.f, q2 = 0.f;

    const bool interior =
        ((unsigned)(m.x - 8) <= (HW - D)) & ((unsigned)(m.y - 8) <= (HW - D)) &
        ((unsigned)(m.z - 8) <= (HW - D)) & ((unsigned)(m.w - 8) <= (HW - D));

    if (interior) {
        // ---- fast path: no per-element bounds checks ----
        const float* p1 = ib1 + (m.y - 8) * HW + (m.x - 8);
        const float* p2 = ib2 + (m.w - 8) * HW + (m.z - 8);
        int c   = c0;
        int d   = r0 * HW + c0;          // gmem offset (row-major walk)
        int sts = c0 * D + r0;           // transposed smem index = c*17 + r
        #pragma unroll
        for (int t = 0; t < 10; ++t) {
            if (t < 9 || lane == 0) {
                const float v1 = __ldg(p1 + d);
                const float v2 = __ldg(p2 + d);
                Tw[sts]         = v1;
                Tw[PATCH + sts] = v2;
                s1 += v1; q1 = fmaf(v1, v1, q1);
                s2 += v2; q2 = fmaf(v2, v2, q2);
            }
            // advance idx by 32: c += 15, r += 1 (+carry: c -= 17, r += 1)
            c   += 15;
            d   += HW + 15;              // +1039
            sts += 15 * D + 1;           // +256
            if (c >= D) {
                c   -= D;
                d   += HW - D;           // +1007  (total carry step: +2046)
                sts -= D * D - 1;        // -288   (c: -17*17, r: +1)
            }
        }
    } else {
        // ---- slow path: per-element zero-padding bounds checks ----
        const int x1 = m.x - 8, y1 = m.y - 8;
        const int x2 = m.z - 8, y2 = m.w - 8;
        int c = c0, r = r0;
        int sts = c0 * D + r0;
        #pragma unroll
        for (int t = 0; t < 10; ++t) {
            if (t < 9 || lane == 0) {
                const int yy1 = y1 + r, xx1 = x1 + c;
                const int yy2 = y2 + r, xx2 = x2 + c;
                float v1 = 0.f, v2 = 0.f;
                if (((unsigned)yy1 < HW) & ((unsigned)xx1 < HW))
                    v1 = __ldg(ib1 + yy1 * HW + xx1);
                if (((unsigned)yy2 < HW) & ((unsigned)xx2 < HW))
                    v2 = __ldg(ib2 + yy2 * HW + xx2);
                Tw[sts]         = v1;
                Tw[PATCH + sts] = v2;
                s1 += v1; q1 = fmaf(v1, v1, q1);
                s2 += v2; q2 = fmaf(v2, v2, q2);
            }
            c += 15; r += 1; sts += 15 * D + 1;
            if (c >= D) { c -= D; r += 1; sts -= D * D - 1; }
        }
    }

    // ---- warp reductions (both patches) ----
    #pragma unroll
    for (int o = 16; o > 0; o >>= 1) {
        s1 += __shfl_xor_sync(0xffffffffu, s1, o);
        q1 += __shfl_xor_sync(0xffffffffu, q1, o);
        s2 += __shfl_xor_sync(0xffffffffu, s2, o);
        q2 += __shfl_xor_sync(0xffffffffu, q2, o);
    }
    const float mean1 = s1 * (1.0f / PATCH);
    const float mean2 = s2 * (1.0f / PATCH);
    float var1 = fmaxf((q1 - (float)PATCH * mean1 * mean1) * (1.0f / (PATCH - 1)), 0.f);
    float var2 = fmaxf((q2 - (float)PATCH * mean2 * mean2) * (1.0f / (PATCH - 1)), 0.f);
    const float inv1 = 1.0f / (sqrtf(var1) + 1e-4f);
    const float inv2 = 1.0f / (sqrtf(var2) + 1e-4f);

    __syncwarp();

    // ---- vectorized normalized write: 289 float2 over 578 contiguous floats ----
    float2* __restrict__ ob = (float2*)(out + (size_t)bn * (2 * PATCH));
    const float2* __restrict__ Ts = (const float2*)Tw;   // 8B aligned

    #pragma unroll
    for (int t = 0; t < 10; ++t) {
        const int k = t * 32 + lane;      // float2 index, valid k < 289
        if (t < 9 || lane == 0) {
            const float2 v = Ts[k];
            float mLo, iLo, mHi, iHi;
            if (t < 4)      { mLo = mean1; iLo = inv1; mHi = mean1; iHi = inv1; }
            else if (t > 4) { mLo = mean2; iLo = inv2; mHi = mean2; iHi = inv2; }
            else {
                // boundary tile: elem 2k is patch1 iff k<=144; elem 2k+1 patch1 iff k<=143
                mLo = (k <= 144) ? mean1 : mean2;  iLo = (k <= 144) ? inv1 : inv2;
                mHi = (k <= 143) ? mean1 : mean2;  iHi = (k <= 143) ? inv1 : inv2;
            }
            float2 w;
            w.x = (v.x - mLo) * iLo;
            w.y = (v.y - mHi) * iHi;
            __stcs(&ob[k], w);
        }
    }
}

extern "C" void kernel_launch(void* const* d_in, const int* in_sizes, int n_in,
                              void* d_out, int out_size)
{
    const float* img1    = (const float*)d_in[0];
    const float* img2    = (const float*)d_in[1];
    const int*   matches = (const int*)d_in[2];
    float*       out     = (float*)d_out;

    const int total_matches = BATCH * NMATCH;           // 32768
    const int blocks = total_matches / WPB;             // 8192

    extract_patch_kernel<<<blocks, THREADS>>>(img1, img2, matches, out);
}